// round 13
// baseline (speedup 1.0000x reference)
#include <cuda_runtime.h>
#include <cuda_bf16.h>
#include <cstdint>

#define BATCH 2
#define CH 256
#define NTOK 4096
#define NHEAD 8
#define HDIM 32
#define SCALE_LOG2E 0.2550316805267167f      // (1/sqrt(32)) * log2(e)
#define ONES_BF16X2 0x3F803F80u              // bf16 {1.0, 1.0}

// ---------------- scratch (no allocations allowed) ----------------
__device__ __nv_bfloat16 g_tn[BATCH * CH * NTOK];               // layernorm out, [b][c][n] bf16
__device__ uint8_t       g_q8[BATCH * NHEAD * NTOK * HDIM];     // e4m3, pre-scaled by SCALE_LOG2E
__device__ uint8_t       g_k8[BATCH * NHEAD * NTOK * HDIM];     // e4m3
__device__ __nv_bfloat16 g_v [BATCH * NHEAD * NTOK * HDIM];     // bf16
__device__ __nv_bfloat16 g_ao[BATCH * NTOK * CH];               // attn out, [b][n][c] bf16

// ---------------- helpers ----------------
__device__ __forceinline__ void ldsm_x4(uint32_t* r, uint32_t saddr) {
    asm volatile("ldmatrix.sync.aligned.m8n8.x4.shared.b16 {%0,%1,%2,%3}, [%4];"
                 : "=r"(r[0]), "=r"(r[1]), "=r"(r[2]), "=r"(r[3]) : "r"(saddr));
}
__device__ __forceinline__ void ldsm_x4_trans(uint32_t* r, uint32_t saddr) {
    asm volatile("ldmatrix.sync.aligned.m8n8.x4.trans.shared.b16 {%0,%1,%2,%3}, [%4];"
                 : "=r"(r[0]), "=r"(r[1]), "=r"(r[2]), "=r"(r[3]) : "r"(saddr));
}
__device__ __forceinline__ void mma16816(float* c, const uint32_t* a, uint32_t b0, uint32_t b1) {
    asm volatile("mma.sync.aligned.m16n8k16.row.col.f32.bf16.bf16.f32 "
                 "{%0,%1,%2,%3}, {%4,%5,%6,%7}, {%8,%9}, {%0,%1,%2,%3};"
                 : "+f"(c[0]), "+f"(c[1]), "+f"(c[2]), "+f"(c[3])
                 : "r"(a[0]), "r"(a[1]), "r"(a[2]), "r"(a[3]), "r"(b0), "r"(b1));
}
__device__ __forceinline__ void mma16832_fp8(float* c, const uint32_t* a, uint32_t b0, uint32_t b1) {
    asm volatile("mma.sync.aligned.m16n8k32.row.col.f32.e4m3.e4m3.f32 "
                 "{%0,%1,%2,%3}, {%4,%5,%6,%7}, {%8,%9}, {%0,%1,%2,%3};"
                 : "+f"(c[0]), "+f"(c[1]), "+f"(c[2]), "+f"(c[3])
                 : "r"(a[0]), "r"(a[1]), "r"(a[2]), "r"(a[3]), "r"(b0), "r"(b1));
}
__device__ __forceinline__ uint32_t pack_bf16x2(float lo, float hi) {
    uint32_t r;
    asm("cvt.rn.bf16x2.f32 %0, %1, %2;" : "=r"(r) : "f"(hi), "f"(lo));
    return r;
}
__device__ __forceinline__ uint16_t pack_e4m3x2(float lo, float hi) {
    uint16_t r;
    asm("cvt.rn.satfinite.e4m3x2.f32 %0, %1, %2;" : "=h"(r) : "f"(hi), "f"(lo));
    return r;
}
__device__ __forceinline__ uint32_t ex2_bf16x2(uint32_t u) {
    uint32_t r;
    asm("ex2.approx.ftz.bf16x2 %0, %1;" : "=r"(r) : "r"(u));
    return r;
}
__device__ __forceinline__ void cp_async16(uint32_t saddr, const void* gptr) {
    asm volatile("cp.async.cg.shared.global [%0], [%1], 16;" :: "r"(saddr), "l"(gptr));
}
#define CP_COMMIT() asm volatile("cp.async.commit_group;")
#define CP_WAIT1()  asm volatile("cp.async.wait_group 1;")

// ---------------- kernel 1: LayerNorm, block-parallel (R8) ----------------
__global__ void __launch_bounds__(256) ln_kernel(const float* __restrict__ x,
                                                 const float* __restrict__ gamma,
                                                 const float* __restrict__ beta) {
    const int b   = blockIdx.y;
    const int n0  = blockIdx.x * 64;
    const int tid = threadIdx.x;
    const int tok = tid & 63;
    const int grp = tid >> 6;

    __shared__ float red_s [4][64];
    __shared__ float red_ss[4][64];
    __shared__ float mu_s[64], rs_s[64];

    const float* xb = x + (size_t)b * CH * NTOK + n0 + tok;

    float s = 0.f, ss = 0.f;
#pragma unroll 16
    for (int i = 0; i < 64; i++) {
        float v = xb[(size_t)(grp * 64 + i) * NTOK];
        s += v; ss += v * v;
    }
    red_s[grp][tok]  = s;
    red_ss[grp][tok] = ss;
    __syncthreads();

    if (tid < 64) {
        float st = red_s[0][tid] + red_s[1][tid] + red_s[2][tid] + red_s[3][tid];
        float sst = red_ss[0][tid] + red_ss[1][tid] + red_ss[2][tid] + red_ss[3][tid];
        float mu = st * (1.0f / CH);
        float var = sst * (1.0f / CH) - mu * mu;
        mu_s[tid] = mu;
        rs_s[tid] = rsqrtf(var + 1e-5f);
    }
    __syncthreads();

    const float mu = mu_s[tok];
    const float rs = rs_s[tok];
    __nv_bfloat16* tb = g_tn + (size_t)b * CH * NTOK + n0 + tok;
#pragma unroll 16
    for (int i = 0; i < 64; i++) {
        int c = grp * 64 + i;
        float v = xb[(size_t)c * NTOK];
        tb[(size_t)c * NTOK] = __float2bfloat16_rn((v - mu) * rs * __ldg(&gamma[c]) + __ldg(&beta[c]));
    }
}

// ---------------- kernel 2: QKV GEMM, o-tile 128, 256 threads, register-staged ----------------
// Halves A-tile L2 redundancy (6 o-blocks instead of 12). Each warp: one m16 x 16 n8 tiles.
__global__ void __launch_bounds__(256) qkv_mma_kernel(const float* __restrict__ w) {
    const int b  = blockIdx.z;
    const int m0 = blockIdx.x * 128;
    const int o0 = blockIdx.y * 128;
    const int tid  = threadIdx.x;
    const int warp = tid >> 5;   // 0..7, m16 tile index
    const int lane = tid & 31;

    __shared__ __nv_bfloat16 As[2][32 * 136];   // [k][m]
    __shared__ __nv_bfloat16 Bs[2][128 * 40];   // [o][k]

    float acc[16][4];
#pragma unroll
    for (int nt = 0; nt < 16; nt++) {
#pragma unroll
        for (int c = 0; c < 4; c++) { acc[nt][c] = 0.f; }
    }

    const __nv_bfloat16* aBase = g_tn + (size_t)b * CH * NTOK;

    uint4  areg[2];
    float4 breg[4];
    // prologue: k-slab 0
#pragma unroll
    for (int ii = 0; ii < 2; ii++) {
        int idx = tid + 256 * ii;
        int k   = idx >> 4;
        int mc  = (idx & 15) * 8;
        areg[ii] = *(const uint4*)&aBase[(size_t)k * NTOK + m0 + mc];
    }
#pragma unroll
    for (int ii = 0; ii < 4; ii++) {
        int idx = tid + 256 * ii;
        int o   = idx >> 3;
        int kq  = (idx & 7) * 4;
        breg[ii] = *(const float4*)&w[(size_t)(o0 + o) * CH + kq];
    }
#pragma unroll
    for (int ii = 0; ii < 2; ii++) {
        int idx = tid + 256 * ii;
        int k   = idx >> 4;
        int mc  = (idx & 15) * 8;
        *(uint4*)&As[0][k * 136 + mc] = areg[ii];
    }
#pragma unroll
    for (int ii = 0; ii < 4; ii++) {
        int idx = tid + 256 * ii;
        int o   = idx >> 3;
        int kq  = (idx & 7) * 4;
        __nv_bfloat16 tmp[4];
        tmp[0] = __float2bfloat16_rn(breg[ii].x);
        tmp[1] = __float2bfloat16_rn(breg[ii].y);
        tmp[2] = __float2bfloat16_rn(breg[ii].z);
        tmp[3] = __float2bfloat16_rn(breg[ii].w);
        *(uint2*)&Bs[0][o * 40 + kq] = *(uint2*)tmp;
    }
    __syncthreads();

    const int KITERS = CH / 32;   // 8
    for (int ki = 0; ki < KITERS; ki++) {
        const int buf = ki & 1;
        if (ki + 1 < KITERS) {
            int kt = (ki + 1) * 32;
#pragma unroll
            for (int ii = 0; ii < 2; ii++) {
                int idx = tid + 256 * ii;
                int k   = idx >> 4;
                int mc  = (idx & 15) * 8;
                areg[ii] = *(const uint4*)&aBase[(size_t)(kt + k) * NTOK + m0 + mc];
            }
#pragma unroll
            for (int ii = 0; ii < 4; ii++) {
                int idx = tid + 256 * ii;
                int o   = idx >> 3;
                int kq  = (idx & 7) * 4;
                breg[ii] = *(const float4*)&w[(size_t)(o0 + o) * CH + kt + kq];
            }
        }

        // A-fragments for this warp's m16 tile (k0..15 and k16..31)
        uint32_t af0[4], af1[4];
        {
            int mrow0 = warp * 16;
            uint32_t a0 = (uint32_t)__cvta_generic_to_shared(
                &As[buf][((lane & 7) + ((lane & 16) >> 1)) * 136 + mrow0 + (lane & 8)]);
            uint32_t a1 = (uint32_t)__cvta_generic_to_shared(
                &As[buf][(16 + (lane & 7) + ((lane & 16) >> 1)) * 136 + mrow0 + (lane & 8)]);
            ldsm_x4_trans(af0, a0);
            ldsm_x4_trans(af1, a1);
        }
#pragma unroll
        for (int nt = 0; nt < 16; nt++) {
            uint32_t kb[4];
            uint32_t baddr = (uint32_t)__cvta_generic_to_shared(
                &Bs[buf][(nt * 8 + (lane & 7)) * 40 + (lane >> 3) * 8]);
            ldsm_x4(kb, baddr);
            mma16816(acc[nt], af0, kb[0], kb[1]);
            mma16816(acc[nt], af1, kb[2], kb[3]);
        }

        if (ki + 1 < KITERS) {
#pragma unroll
            for (int ii = 0; ii < 2; ii++) {
                int idx = tid + 256 * ii;
                int k   = idx >> 4;
                int mc  = (idx & 15) * 8;
                *(uint4*)&As[buf ^ 1][k * 136 + mc] = areg[ii];
            }
#pragma unroll
            for (int ii = 0; ii < 4; ii++) {
                int idx = tid + 256 * ii;
                int o   = idx >> 3;
                int kq  = (idx & 7) * 4;
                __nv_bfloat16 tmp[4];
                tmp[0] = __float2bfloat16_rn(breg[ii].x);
                tmp[1] = __float2bfloat16_rn(breg[ii].y);
                tmp[2] = __float2bfloat16_rn(breg[ii].z);
                tmp[3] = __float2bfloat16_rn(breg[ii].w);
                *(uint2*)&Bs[buf ^ 1][o * 40 + kq] = *(uint2*)tmp;
            }
        }
        __syncthreads();
    }

    // epilogue (o-tile 128 lies entirely inside one of q/k/v)
    const int which = o0 >> 8;                   // 0:q 1:k 2:v
    if (which < 2) {
        const float sc = (which == 0) ? SCALE_LOG2E : 1.0f;
        uint8_t* outp = (which == 0) ? g_q8 : g_k8;
#pragma unroll
        for (int nt = 0; nt < 16; nt++) {
            int o  = o0 + nt * 8 + 2 * (lane & 3);
            int h  = (o >> 5) & 7;
            int dd = o & 31;
            int n_lo = m0 + warp * 16 + (lane >> 2);
            uint16_t lo = pack_e4m3x2(acc[nt][0] * sc, acc[nt][1] * sc);
            uint16_t hi = pack_e4m3x2(acc[nt][2] * sc, acc[nt][3] * sc);
            *(uint16_t*)&outp[((size_t)(b * NHEAD + h) * NTOK + n_lo) * HDIM + dd]     = lo;
            *(uint16_t*)&outp[((size_t)(b * NHEAD + h) * NTOK + n_lo + 8) * HDIM + dd] = hi;
        }
    } else {
#pragma unroll
        for (int nt = 0; nt < 16; nt++) {
            int o  = o0 + nt * 8 + 2 * (lane & 3);
            int h  = (o >> 5) & 7;
            int dd = o & 31;
            int n_lo = m0 + warp * 16 + (lane >> 2);
            uint32_t lo = pack_bf16x2(acc[nt][0], acc[nt][1]);
            uint32_t hi = pack_bf16x2(acc[nt][2], acc[nt][3]);
            *(uint32_t*)&g_v[((size_t)(b * NHEAD + h) * NTOK + n_lo) * HDIM + dd]     = lo;
            *(uint32_t*)&g_v[((size_t)(b * NHEAD + h) * NTOK + n_lo + 8) * HDIM + dd] = hi;
        }
    }
}

// ---------------- kernel 3: flash attention, BM=128 / BN=128, no softmax (R12) ----------------
__global__ void __launch_bounds__(128) flash_mma_kernel() {
    const int b  = blockIdx.z;
    const int h  = blockIdx.y;
    const int n0 = blockIdx.x * 128;
    const int tid  = threadIdx.x;
    const int warp = tid >> 5;
    const int lane = tid & 31;

    __shared__ uint8_t       Qs[128 * 48];
    __shared__ uint8_t       Ks[3][128 * 48];
    __shared__ __nv_bfloat16 Vs[3][128 * 40];

    const uint8_t* qsrc = g_q8 + ((size_t)(b * NHEAD + h) * NTOK + n0) * HDIM;
    const uint8_t* ksrc = g_k8 + (size_t)(b * NHEAD + h) * NTOK * HDIM;
    const __nv_bfloat16* vsrc = g_v + (size_t)(b * NHEAD + h) * NTOK * HDIM;

#pragma unroll
    for (int ii = 0; ii < 2; ii++) {
        int idx = tid + 128 * ii;
        int row = idx >> 1;
        int cc  = idx & 1;
        *(uint4*)&Qs[row * 48 + cc * 16] = *(const uint4*)&qsrc[(size_t)row * 32 + cc * 16];
    }

#pragma unroll
    for (int stg = 0; stg < 2; stg++) {
        int j = stg * 128;
#pragma unroll
        for (int ii = 0; ii < 2; ii++) {
            int idx = tid + 128 * ii;
            int row = idx >> 1;
            int cc  = idx & 1;
            cp_async16((uint32_t)__cvta_generic_to_shared(&Ks[stg][row * 48 + cc * 16]),
                       &ksrc[(size_t)(j + row) * 32 + cc * 16]);
        }
#pragma unroll
        for (int ii = 0; ii < 4; ii++) {
            int idx = tid + 128 * ii;
            int row = idx >> 2;
            int cc  = idx & 3;
            cp_async16((uint32_t)__cvta_generic_to_shared(&Vs[stg][row * 40 + cc * 8]),
                       &vsrc[(size_t)(j + row) * 32 + cc * 8]);
        }
        CP_COMMIT();
    }
    __syncthreads();

    uint32_t aq[2][4];
#pragma unroll
    for (int mt = 0; mt < 2; mt++) {
        uint32_t base = (uint32_t)__cvta_generic_to_shared(
            &Qs[(warp * 32 + mt * 16 + (lane & 15)) * 48 + (lane >> 4) * 16]);
        ldsm_x4(aq[mt], base);
    }

    float lacc[2][4];
    float o_[2][4][4];
#pragma unroll
    for (int mt = 0; mt < 2; mt++) {
#pragma unroll
        for (int c = 0; c < 4; c++) { lacc[mt][c] = 0.f; }
#pragma unroll
        for (int dt = 0; dt < 4; dt++) {
#pragma unroll
            for (int c = 0; c < 4; c++) { o_[mt][dt][c] = 0.f; }
        }
    }

    const int NITER = NTOK / 128;   // 32
    int st = 0;
    for (int it = 0; it < NITER; it++) {
        CP_WAIT1();
        __syncthreads();

        if (it + 2 < NITER) {
            int stn = (st + 2 >= 3) ? st - 1 : st + 2;
            int j = (it + 2) * 128;
#pragma unroll
            for (int ii = 0; ii < 2; ii++) {
                int idx = tid + 128 * ii;
                int row = idx >> 1;
                int cc  = idx & 1;
                cp_async16((uint32_t)__cvta_generic_to_shared(&Ks[stn][row * 48 + cc * 16]),
                           &ksrc[(size_t)(j + row) * 32 + cc * 16]);
            }
#pragma unroll
            for (int ii = 0; ii < 4; ii++) {
                int idx = tid + 128 * ii;
                int row = idx >> 2;
                int cc  = idx & 3;
                cp_async16((uint32_t)__cvta_generic_to_shared(&Vs[stn][row * 40 + cc * 8]),
                           &vsrc[(size_t)(j + row) * 32 + cc * 8]);
            }
        }
        CP_COMMIT();

        const uint8_t* KsS = Ks[st];
        const __nv_bfloat16* VsS = Vs[st];
        st = (st + 1 == 3) ? 0 : st + 1;

        uint32_t pa[2][8][4];
#pragma unroll
        for (int ntp = 0; ntp < 8; ntp++) {
            uint32_t kbf[4];
            uint32_t kaddr = (uint32_t)__cvta_generic_to_shared(
                &KsS[(ntp * 16 + (lane & 15)) * 48 + (lane >> 4) * 16]);
            ldsm_x4(kbf, kaddr);
#pragma unroll
            for (int mt = 0; mt < 2; mt++) {
                float s0[4] = {0.f, 0.f, 0.f, 0.f};
                float s1[4] = {0.f, 0.f, 0.f, 0.f};
                mma16832_fp8(s0, aq[mt], kbf[0], kbf[2]);
                mma16832_fp8(s1, aq[mt], kbf[1], kbf[3]);
                pa[mt][ntp][0] = ex2_bf16x2(pack_bf16x2(s0[0], s0[1]));
                pa[mt][ntp][1] = ex2_bf16x2(pack_bf16x2(s0[2], s0[3]));
                pa[mt][ntp][2] = ex2_bf16x2(pack_bf16x2(s1[0], s1[1]));
                pa[mt][ntp][3] = ex2_bf16x2(pack_bf16x2(s1[2], s1[3]));
            }
        }

#pragma unroll
        for (int kc = 0; kc < 8; kc++) {
#pragma unroll
            for (int mt = 0; mt < 2; mt++) {
                mma16816(lacc[mt], pa[mt][kc], ONES_BF16X2, ONES_BF16X2);
            }
        }

#pragma unroll
        for (int kc = 0; kc < 8; kc++) {
#pragma unroll
            for (int db = 0; db < 2; db++) {
                uint32_t vb[4];
                uint32_t vaddr = (uint32_t)__cvta_generic_to_shared(
                    &VsS[(kc * 16 + (lane & 15)) * 40 + db * 16 + (lane >> 4) * 8]);
                ldsm_x4_trans(vb, vaddr);
#pragma unroll
                for (int mt = 0; mt < 2; mt++) {
                    mma16816(o_[mt][db * 2],     pa[mt][kc], vb[0], vb[1]);
                    mma16816(o_[mt][db * 2 + 1], pa[mt][kc], vb[2], vb[3]);
                }
            }
        }
    }

#pragma unroll
    for (int mt = 0; mt < 2; mt++) {
        float inv0 = 1.0f / lacc[mt][0];
        float inv1 = 1.0f / lacc[mt][2];
        int r0 = n0 + warp * 32 + mt * 16 + (lane >> 2);
#pragma unroll
        for (int dt = 0; dt < 4; dt++) {
            int col = h * 32 + dt * 8 + 2 * (lane & 3);
            uint32_t lo = pack_bf16x2(o_[mt][dt][0] * inv0, o_[mt][dt][1] * inv0);
            uint32_t hi = pack_bf16x2(o_[mt][dt][2] * inv1, o_[mt][dt][3] * inv1);
            *(uint32_t*)&g_ao[(size_t)(b * NTOK + r0) * CH + col]     = lo;
            *(uint32_t*)&g_ao[(size_t)(b * NTOK + r0 + 8) * CH + col] = hi;
        }
    }
}

// ---------------- kernel 4: proj GEMM, m-tile 32, smem-staged float4 epilogue ----------------
__global__ void __launch_bounds__(128) proj_mma_kernel(const float* __restrict__ x,
                                                       const float* __restrict__ w,
                                                       const float* __restrict__ bias,
                                                       float* __restrict__ out) {
    const int b  = blockIdx.z;
    const int m0 = blockIdx.x * 32;
    const int o0 = blockIdx.y * 64;
    const int tid  = threadIdx.x;
    const int warp = tid >> 5;
    const int lane = tid & 31;
    const int mwarp = warp & 1;
    const int nwarp = warp >> 1;

    __shared__ __nv_bfloat16 As[2][32 * 40];
    __shared__ __nv_bfloat16 Bs[2][64 * 40];
    __shared__ float Es[64 * 33];              // [o_local][n_local] staging for epilogue

    float acc[4][4];
#pragma unroll
    for (int nt = 0; nt < 4; nt++) {
#pragma unroll
        for (int c = 0; c < 4; c++) { acc[nt][c] = 0.f; }
    }

    const __nv_bfloat16* aBase = g_ao + (size_t)b * NTOK * CH;

    uint4  areg;
    float4 breg[4];
    {
        int m  = tid >> 2;
        int kk = (tid & 3) * 8;
        areg = *(const uint4*)&aBase[(size_t)(m0 + m) * CH + kk];
#pragma unroll
        for (int ii = 0; ii < 4; ii++) {
            int idx = tid + 128 * ii;
            int o   = idx >> 3;
            int kq  = (idx & 7) * 4;
            breg[ii] = *(const float4*)&w[(size_t)(o0 + o) * CH + kq];
        }
    }
    {
        int m  = tid >> 2;
        int kk = (tid & 3) * 8;
        *(uint4*)&As[0][m * 40 + kk] = areg;
#pragma unroll
        for (int ii = 0; ii < 4; ii++) {
            int idx = tid + 128 * ii;
            int o   = idx >> 3;
            int kq  = (idx & 7) * 4;
            __nv_bfloat16 tmp[4];
            tmp[0] = __float2bfloat16_rn(breg[ii].x);
            tmp[1] = __float2bfloat16_rn(breg[ii].y);
            tmp[2] = __float2bfloat16_rn(breg[ii].z);
            tmp[3] = __float2bfloat16_rn(breg[ii].w);
            *(uint2*)&Bs[0][o * 40 + kq] = *(uint2*)tmp;
        }
    }
    __syncthreads();

    const int KITERS = CH / 32;
    for (int ki = 0; ki < KITERS; ki++) {
        const int buf = ki & 1;
        if (ki + 1 < KITERS) {
            int kt = (ki + 1) * 32;
            int m  = tid >> 2;
            int kk = (tid & 3) * 8;
            areg = *(const uint4*)&aBase[(size_t)(m0 + m) * CH + kt + kk];
#pragma unroll
            for (int ii = 0; ii < 4; ii++) {
                int idx = tid + 128 * ii;
                int o   = idx >> 3;
                int kq  = (idx & 7) * 4;
                breg[ii] = *(const float4*)&w[(size_t)(o0 + o) * CH + kt + kq];
            }
        }

        uint32_t kb[4][4];
#pragma unroll
        for (int nt = 0; nt < 4; nt++) {
            uint32_t baddr = (uint32_t)__cvta_generic_to_shared(
                &Bs[buf][(nwarp * 32 + nt * 8 + (lane & 7)) * 40 + (lane >> 3) * 8]);
            ldsm_x4(kb[nt], baddr);
        }
        {
            uint32_t abase = (uint32_t)__cvta_generic_to_shared(
                &As[buf][(mwarp * 16 + (lane & 15)) * 40 + (lane >> 4) * 8]);
            uint32_t af0[4], af1[4];
            ldsm_x4(af0, abase);
            ldsm_x4(af1, abase + 32);
#pragma unroll
            for (int nt = 0; nt < 4; nt++) {
                mma16816(acc[nt], af0, kb[nt][0], kb[nt][1]);
                mma16816(acc[nt], af1, kb[nt][2], kb[nt][3]);
            }
        }

        if (ki + 1 < KITERS) {
            int m  = tid >> 2;
            int kk = (tid & 3) * 8;
            *(uint4*)&As[buf ^ 1][m * 40 + kk] = areg;
#pragma unroll
            for (int ii = 0; ii < 4; ii++) {
                int idx = tid + 128 * ii;
                int o   = idx >> 3;
                int kq  = (idx & 7) * 4;
                __nv_bfloat16 tmp[4];
                tmp[0] = __float2bfloat16_rn(breg[ii].x);
                tmp[1] = __float2bfloat16_rn(breg[ii].y);
                tmp[2] = __float2bfloat16_rn(breg[ii].z);
                tmp[3] = __float2bfloat16_rn(breg[ii].w);
                *(uint2*)&Bs[buf ^ 1][o * 40 + kq] = *(uint2*)tmp;
            }
        }
        __syncthreads();
    }

    // stage acc -> Es[o][n]
#pragma unroll
    for (int nt = 0; nt < 4; nt++) {
        int o_l = nwarp * 32 + nt * 8 + 2 * (lane & 3);
        int n_l = mwarp * 16 + (lane >> 2);
        Es[o_l * 33 + n_l]           = acc[nt][0];
        Es[(o_l + 1) * 33 + n_l]     = acc[nt][1];
        Es[o_l * 33 + n_l + 8]       = acc[nt][2];
        Es[(o_l + 1) * 33 + n_l + 8] = acc[nt][3];
    }
    __syncthreads();

    // coalesced float4 epilogue: out[b][o][n] = Es + x + bias
#pragma unroll
    for (int ii = 0; ii < 4; ii++) {
        int idx = tid + 128 * ii;
        int o_l = idx >> 3;
        int n4  = (idx & 7) * 4;
        float bp = __ldg(&bias[o0 + o_l]);
        size_t base = (size_t)b * CH * NTOK + (size_t)(o0 + o_l) * NTOK + m0 + n4;
        float4 xv = *(const float4*)&x[base];
        float4 r;
        r.x = Es[o_l * 33 + n4 + 0] + xv.x + bp;
        r.y = Es[o_l * 33 + n4 + 1] + xv.y + bp;
        r.z = Es[o_l * 33 + n4 + 2] + xv.z + bp;
        r.w = Es[o_l * 33 + n4 + 3] + xv.w + bp;
        *(float4*)&out[base] = r;
    }
}

// ---------------- launch ----------------
extern "C" void kernel_launch(void* const* d_in, const int* in_sizes, int n_in,
                              void* d_out, int out_size) {
    const float* x      = (const float*)d_in[0];
    const float* gamma  = (const float*)d_in[1];
    const float* beta   = (const float*)d_in[2];
    const float* w_qkv  = (const float*)d_in[3];
    const float* w_proj = (const float*)d_in[4];
    const float* b_proj = (const float*)d_in[5];
    float* out = (float*)d_out;

    ln_kernel<<<dim3(NTOK / 64, BATCH), 256>>>(x, gamma, beta);
    qkv_mma_kernel<<<dim3(NTOK / 128, 6, BATCH), 256>>>(w_qkv);
    flash_mma_kernel<<<dim3(NTOK / 128, NHEAD, BATCH), 128>>>();
    proj_mma_kernel<<<dim3(NTOK / 32, CH / 64, BATCH), 128>>>(x, w_proj, b_proj, out);
}

// round 14
// speedup vs baseline: 1.0265x; 1.0265x over previous
#include <cuda_runtime.h>
#include <cuda_bf16.h>
#include <cstdint>

#define BATCH 2
#define CH 256
#define NTOK 4096
#define NHEAD 8
#define HDIM 32
#define SCALE_LOG2E 0.2550316805267167f      // (1/sqrt(32)) * log2(e)
#define ONES_BF16X2 0x3F803F80u              // bf16 {1.0, 1.0}

// ---------------- scratch (no allocations allowed) ----------------
__device__ __nv_bfloat16 g_tn[BATCH * CH * NTOK];               // layernorm out, [b][c][n] bf16
__device__ uint8_t       g_q8[BATCH * NHEAD * NTOK * HDIM];     // e4m3, pre-scaled by SCALE_LOG2E
__device__ uint8_t       g_k8[BATCH * NHEAD * NTOK * HDIM];     // e4m3
__device__ __nv_bfloat16 g_v [BATCH * NHEAD * NTOK * HDIM];     // bf16
__device__ __nv_bfloat16 g_ao[BATCH * NTOK * CH];               // attn out, [b][n][c] bf16

// ---------------- helpers ----------------
__device__ __forceinline__ void ldsm_x4(uint32_t* r, uint32_t saddr) {
    asm volatile("ldmatrix.sync.aligned.m8n8.x4.shared.b16 {%0,%1,%2,%3}, [%4];"
                 : "=r"(r[0]), "=r"(r[1]), "=r"(r[2]), "=r"(r[3]) : "r"(saddr));
}
__device__ __forceinline__ void ldsm_x4_trans(uint32_t* r, uint32_t saddr) {
    asm volatile("ldmatrix.sync.aligned.m8n8.x4.trans.shared.b16 {%0,%1,%2,%3}, [%4];"
                 : "=r"(r[0]), "=r"(r[1]), "=r"(r[2]), "=r"(r[3]) : "r"(saddr));
}
__device__ __forceinline__ void mma16816(float* c, const uint32_t* a, uint32_t b0, uint32_t b1) {
    asm volatile("mma.sync.aligned.m16n8k16.row.col.f32.bf16.bf16.f32 "
                 "{%0,%1,%2,%3}, {%4,%5,%6,%7}, {%8,%9}, {%0,%1,%2,%3};"
                 : "+f"(c[0]), "+f"(c[1]), "+f"(c[2]), "+f"(c[3])
                 : "r"(a[0]), "r"(a[1]), "r"(a[2]), "r"(a[3]), "r"(b0), "r"(b1));
}
__device__ __forceinline__ void mma16832_fp8(float* c, const uint32_t* a, uint32_t b0, uint32_t b1) {
    asm volatile("mma.sync.aligned.m16n8k32.row.col.f32.e4m3.e4m3.f32 "
                 "{%0,%1,%2,%3}, {%4,%5,%6,%7}, {%8,%9}, {%0,%1,%2,%3};"
                 : "+f"(c[0]), "+f"(c[1]), "+f"(c[2]), "+f"(c[3])
                 : "r"(a[0]), "r"(a[1]), "r"(a[2]), "r"(a[3]), "r"(b0), "r"(b1));
}
__device__ __forceinline__ uint32_t pack_bf16x2(float lo, float hi) {
    uint32_t r;
    asm("cvt.rn.bf16x2.f32 %0, %1, %2;" : "=r"(r) : "f"(hi), "f"(lo));
    return r;
}
__device__ __forceinline__ uint16_t pack_e4m3x2(float lo, float hi) {
    uint16_t r;
    asm("cvt.rn.satfinite.e4m3x2.f32 %0, %1, %2;" : "=h"(r) : "f"(hi), "f"(lo));
    return r;
}
__device__ __forceinline__ uint32_t ex2_bf16x2(uint32_t u) {
    uint32_t r;
    asm("ex2.approx.ftz.bf16x2 %0, %1;" : "=r"(r) : "r"(u));
    return r;
}
__device__ __forceinline__ void cp_async16(uint32_t saddr, const void* gptr) {
    asm volatile("cp.async.cg.shared.global [%0], [%1], 16;" :: "r"(saddr), "l"(gptr));
}
#define CP_COMMIT() asm volatile("cp.async.commit_group;")
#define CP_WAIT1()  asm volatile("cp.async.wait_group 1;")

// ---------------- kernel 1: LayerNorm, block-parallel (R8) ----------------
__global__ void __launch_bounds__(256) ln_kernel(const float* __restrict__ x,
                                                 const float* __restrict__ gamma,
                                                 const float* __restrict__ beta) {
    const int b   = blockIdx.y;
    const int n0  = blockIdx.x * 64;
    const int tid = threadIdx.x;
    const int tok = tid & 63;
    const int grp = tid >> 6;

    __shared__ float red_s [4][64];
    __shared__ float red_ss[4][64];
    __shared__ float mu_s[64], rs_s[64];

    const float* xb = x + (size_t)b * CH * NTOK + n0 + tok;

    float s = 0.f, ss = 0.f;
#pragma unroll 16
    for (int i = 0; i < 64; i++) {
        float v = xb[(size_t)(grp * 64 + i) * NTOK];
        s += v; ss += v * v;
    }
    red_s[grp][tok]  = s;
    red_ss[grp][tok] = ss;
    __syncthreads();

    if (tid < 64) {
        float st = red_s[0][tid] + red_s[1][tid] + red_s[2][tid] + red_s[3][tid];
        float sst = red_ss[0][tid] + red_ss[1][tid] + red_ss[2][tid] + red_ss[3][tid];
        float mu = st * (1.0f / CH);
        float var = sst * (1.0f / CH) - mu * mu;
        mu_s[tid] = mu;
        rs_s[tid] = rsqrtf(var + 1e-5f);
    }
    __syncthreads();

    const float mu = mu_s[tok];
    const float rs = rs_s[tok];
    __nv_bfloat16* tb = g_tn + (size_t)b * CH * NTOK + n0 + tok;
#pragma unroll 16
    for (int i = 0; i < 64; i++) {
        int c = grp * 64 + i;
        float v = xb[(size_t)c * NTOK];
        tb[(size_t)c * NTOK] = __float2bfloat16_rn((v - mu) * rs * __ldg(&gamma[c]) + __ldg(&beta[c]));
    }
}

// ---------------- kernel 2: QKV GEMM, register-staged; q/k -> e4m3, v -> bf16 (R12) ----------------
__global__ void __launch_bounds__(128) qkv_mma_kernel(const float* __restrict__ w) {
    const int b  = blockIdx.z;
    const int m0 = blockIdx.x * 128;
    const int o0 = blockIdx.y * 64;
    const int tid  = threadIdx.x;
    const int warp = tid >> 5;
    const int lane = tid & 31;

    __shared__ __nv_bfloat16 As[2][32 * 136];
    __shared__ __nv_bfloat16 Bs[2][64 * 40];

    float acc[2][8][4];
#pragma unroll
    for (int mt = 0; mt < 2; mt++) {
#pragma unroll
        for (int nt = 0; nt < 8; nt++) {
#pragma unroll
            for (int c = 0; c < 4; c++) { acc[mt][nt][c] = 0.f; }
        }
    }

    const __nv_bfloat16* aBase = g_tn + (size_t)b * CH * NTOK;

    uint4  areg[4];
    float4 breg[4];
#pragma unroll
    for (int ii = 0; ii < 4; ii++) {
        int idx = tid + 128 * ii;
        int k   = idx >> 4;
        int mc  = (idx & 15) * 8;
        areg[ii] = *(const uint4*)&aBase[(size_t)k * NTOK + m0 + mc];
        int o   = idx >> 3;
        int kk  = (idx & 7) * 4;
        breg[ii] = *(const float4*)&w[(size_t)(o0 + o) * CH + kk];
    }
#pragma unroll
    for (int ii = 0; ii < 4; ii++) {
        int idx = tid + 128 * ii;
        int k   = idx >> 4;
        int mc  = (idx & 15) * 8;
        *(uint4*)&As[0][k * 136 + mc] = areg[ii];
        int o   = idx >> 3;
        int kk  = (idx & 7) * 4;
        __nv_bfloat16 tmp[4];
        tmp[0] = __float2bfloat16_rn(breg[ii].x);
        tmp[1] = __float2bfloat16_rn(breg[ii].y);
        tmp[2] = __float2bfloat16_rn(breg[ii].z);
        tmp[3] = __float2bfloat16_rn(breg[ii].w);
        *(uint2*)&Bs[0][o * 40 + kk] = *(uint2*)tmp;
    }
    __syncthreads();

    const int KITERS = CH / 32;
    for (int ki = 0; ki < KITERS; ki++) {
        const int buf = ki & 1;
        if (ki + 1 < KITERS) {
            int kt = (ki + 1) * 32;
#pragma unroll
            for (int ii = 0; ii < 4; ii++) {
                int idx = tid + 128 * ii;
                int k   = idx >> 4;
                int mc  = (idx & 15) * 8;
                areg[ii] = *(const uint4*)&aBase[(size_t)(kt + k) * NTOK + m0 + mc];
                int o   = idx >> 3;
                int kk  = (idx & 7) * 4;
                breg[ii] = *(const float4*)&w[(size_t)(o0 + o) * CH + kt + kk];
            }
        }

        uint32_t kb[8][4];
#pragma unroll
        for (int nt = 0; nt < 8; nt++) {
            uint32_t baddr = (uint32_t)__cvta_generic_to_shared(
                &Bs[buf][(nt * 8 + (lane & 7)) * 40 + (lane >> 3) * 8]);
            ldsm_x4(kb[nt], baddr);
        }
#pragma unroll
        for (int ks = 0; ks < 2; ks++) {
            uint32_t af[2][4];
#pragma unroll
            for (int mt = 0; mt < 2; mt++) {
                int mrow0 = warp * 32 + mt * 16;
                uint32_t aaddr = (uint32_t)__cvta_generic_to_shared(
                    &As[buf][(ks * 16 + (lane & 7) + ((lane & 16) >> 1)) * 136 + mrow0 + (lane & 8)]);
                ldsm_x4_trans(af[mt], aaddr);
            }
#pragma unroll
            for (int mt = 0; mt < 2; mt++) {
#pragma unroll
                for (int nt = 0; nt < 8; nt++) {
                    mma16816(acc[mt][nt], af[mt], kb[nt][2 * ks], kb[nt][2 * ks + 1]);
                }
            }
        }

        if (ki + 1 < KITERS) {
#pragma unroll
            for (int ii = 0; ii < 4; ii++) {
                int idx = tid + 128 * ii;
                int k   = idx >> 4;
                int mc  = (idx & 15) * 8;
                *(uint4*)&As[buf ^ 1][k * 136 + mc] = areg[ii];
                int o   = idx >> 3;
                int kk  = (idx & 7) * 4;
                __nv_bfloat16 tmp[4];
                tmp[0] = __float2bfloat16_rn(breg[ii].x);
                tmp[1] = __float2bfloat16_rn(breg[ii].y);
                tmp[2] = __float2bfloat16_rn(breg[ii].z);
                tmp[3] = __float2bfloat16_rn(breg[ii].w);
                *(uint2*)&Bs[buf ^ 1][o * 40 + kk] = *(uint2*)tmp;
            }
        }
        __syncthreads();
    }

    const int which = o0 >> 8;                   // 0:q 1:k 2:v
    if (which < 2) {
        const float sc = (which == 0) ? SCALE_LOG2E : 1.0f;
        uint8_t* outp = (which == 0) ? g_q8 : g_k8;
#pragma unroll
        for (int mt = 0; mt < 2; mt++) {
#pragma unroll
            for (int nt = 0; nt < 8; nt++) {
                int o  = o0 + nt * 8 + 2 * (lane & 3);
                int h  = (o >> 5) & 7;
                int dd = o & 31;
                int n_lo = m0 + warp * 32 + mt * 16 + (lane >> 2);
                uint16_t lo = pack_e4m3x2(acc[mt][nt][0] * sc, acc[mt][nt][1] * sc);
                uint16_t hi = pack_e4m3x2(acc[mt][nt][2] * sc, acc[mt][nt][3] * sc);
                *(uint16_t*)&outp[((size_t)(b * NHEAD + h) * NTOK + n_lo) * HDIM + dd]     = lo;
                *(uint16_t*)&outp[((size_t)(b * NHEAD + h) * NTOK + n_lo + 8) * HDIM + dd] = hi;
            }
        }
    } else {
#pragma unroll
        for (int mt = 0; mt < 2; mt++) {
#pragma unroll
            for (int nt = 0; nt < 8; nt++) {
                int o  = o0 + nt * 8 + 2 * (lane & 3);
                int h  = (o >> 5) & 7;
                int dd = o & 31;
                int n_lo = m0 + warp * 32 + mt * 16 + (lane >> 2);
                uint32_t lo = pack_bf16x2(acc[mt][nt][0], acc[mt][nt][1]);
                uint32_t hi = pack_bf16x2(acc[mt][nt][2], acc[mt][nt][3]);
                *(uint32_t*)&g_v[((size_t)(b * NHEAD + h) * NTOK + n_lo) * HDIM + dd]     = lo;
                *(uint32_t*)&g_v[((size_t)(b * NHEAD + h) * NTOK + n_lo + 8) * HDIM + dd] = hi;
            }
        }
    }
}

// ---------------- kernel 3: flash attention, fused chunk loop (low registers) ----------------
// BM=128 / BN=128, no softmax. Per 16-token chunk: QK fp8 mma -> ex2 -> l-mma -> PV mma,
// so only one chunk of P (8 regs) is live at a time. Regs ~100 -> higher occupancy.
__global__ void __launch_bounds__(128) flash_mma_kernel() {
    const int b  = blockIdx.z;
    const int h  = blockIdx.y;
    const int n0 = blockIdx.x * 128;
    const int tid  = threadIdx.x;
    const int warp = tid >> 5;
    const int lane = tid & 31;

    __shared__ uint8_t       Qs[128 * 48];
    __shared__ uint8_t       Ks[3][128 * 48];
    __shared__ __nv_bfloat16 Vs[3][128 * 40];

    const uint8_t* qsrc = g_q8 + ((size_t)(b * NHEAD + h) * NTOK + n0) * HDIM;
    const uint8_t* ksrc = g_k8 + (size_t)(b * NHEAD + h) * NTOK * HDIM;
    const __nv_bfloat16* vsrc = g_v + (size_t)(b * NHEAD + h) * NTOK * HDIM;

#pragma unroll
    for (int ii = 0; ii < 2; ii++) {
        int idx = tid + 128 * ii;
        int row = idx >> 1;
        int cc  = idx & 1;
        *(uint4*)&Qs[row * 48 + cc * 16] = *(const uint4*)&qsrc[(size_t)row * 32 + cc * 16];
    }

#pragma unroll
    for (int stg = 0; stg < 2; stg++) {
        int j = stg * 128;
#pragma unroll
        for (int ii = 0; ii < 2; ii++) {
            int idx = tid + 128 * ii;
            int row = idx >> 1;
            int cc  = idx & 1;
            cp_async16((uint32_t)__cvta_generic_to_shared(&Ks[stg][row * 48 + cc * 16]),
                       &ksrc[(size_t)(j + row) * 32 + cc * 16]);
        }
#pragma unroll
        for (int ii = 0; ii < 4; ii++) {
            int idx = tid + 128 * ii;
            int row = idx >> 2;
            int cc  = idx & 3;
            cp_async16((uint32_t)__cvta_generic_to_shared(&Vs[stg][row * 40 + cc * 8]),
                       &vsrc[(size_t)(j + row) * 32 + cc * 8]);
        }
        CP_COMMIT();
    }
    __syncthreads();

    uint32_t aq[2][4];
#pragma unroll
    for (int mt = 0; mt < 2; mt++) {
        uint32_t base = (uint32_t)__cvta_generic_to_shared(
            &Qs[(warp * 32 + mt * 16 + (lane & 15)) * 48 + (lane >> 4) * 16]);
        ldsm_x4(aq[mt], base);
    }

    float lacc[2][4];
    float o_[2][4][4];
#pragma unroll
    for (int mt = 0; mt < 2; mt++) {
#pragma unroll
        for (int c = 0; c < 4; c++) { lacc[mt][c] = 0.f; }
#pragma unroll
        for (int dt = 0; dt < 4; dt++) {
#pragma unroll
            for (int c = 0; c < 4; c++) { o_[mt][dt][c] = 0.f; }
        }
    }

    const int NITER = NTOK / 128;   // 32
    int st = 0;
    for (int it = 0; it < NITER; it++) {
        CP_WAIT1();
        __syncthreads();

        if (it + 2 < NITER) {
            int stn = (st + 2 >= 3) ? st - 1 : st + 2;
            int j = (it + 2) * 128;
#pragma unroll
            for (int ii = 0; ii < 2; ii++) {
                int idx = tid + 128 * ii;
                int row = idx >> 1;
                int cc  = idx & 1;
                cp_async16((uint32_t)__cvta_generic_to_shared(&Ks[stn][row * 48 + cc * 16]),
                           &ksrc[(size_t)(j + row) * 32 + cc * 16]);
            }
#pragma unroll
            for (int ii = 0; ii < 4; ii++) {
                int idx = tid + 128 * ii;
                int row = idx >> 2;
                int cc  = idx & 3;
                cp_async16((uint32_t)__cvta_generic_to_shared(&Vs[stn][row * 40 + cc * 8]),
                           &vsrc[(size_t)(j + row) * 32 + cc * 8]);
            }
        }
        CP_COMMIT();

        const uint8_t* KsS = Ks[st];
        const __nv_bfloat16* VsS = Vs[st];
        st = (st + 1 == 3) ? 0 : st + 1;

        // fused per-chunk: QK -> ex2 -> l -> PV   (16 tokens per chunk)
#pragma unroll
        for (int ntp = 0; ntp < 8; ntp++) {
            uint32_t kbf[4];
            uint32_t kaddr = (uint32_t)__cvta_generic_to_shared(
                &KsS[(ntp * 16 + (lane & 15)) * 48 + (lane >> 4) * 16]);
            ldsm_x4(kbf, kaddr);

            uint32_t pa[2][4];
#pragma unroll
            for (int mt = 0; mt < 2; mt++) {
                float s0[4] = {0.f, 0.f, 0.f, 0.f};
                float s1[4] = {0.f, 0.f, 0.f, 0.f};
                mma16832_fp8(s0, aq[mt], kbf[0], kbf[2]);
                mma16832_fp8(s1, aq[mt], kbf[1], kbf[3]);
                pa[mt][0] = ex2_bf16x2(pack_bf16x2(s0[0], s0[1]));
                pa[mt][1] = ex2_bf16x2(pack_bf16x2(s0[2], s0[3]));
                pa[mt][2] = ex2_bf16x2(pack_bf16x2(s1[0], s1[1]));
                pa[mt][3] = ex2_bf16x2(pack_bf16x2(s1[2], s1[3]));
                mma16816(lacc[mt], pa[mt], ONES_BF16X2, ONES_BF16X2);
            }

#pragma unroll
            for (int db = 0; db < 2; db++) {
                uint32_t vb[4];
                uint32_t vaddr = (uint32_t)__cvta_generic_to_shared(
                    &VsS[(ntp * 16 + (lane & 15)) * 40 + db * 16 + (lane >> 4) * 8]);
                ldsm_x4_trans(vb, vaddr);
#pragma unroll
                for (int mt = 0; mt < 2; mt++) {
                    mma16816(o_[mt][db * 2],     pa[mt], vb[0], vb[1]);
                    mma16816(o_[mt][db * 2 + 1], pa[mt], vb[2], vb[3]);
                }
            }
        }
    }

#pragma unroll
    for (int mt = 0; mt < 2; mt++) {
        float inv0 = 1.0f / lacc[mt][0];
        float inv1 = 1.0f / lacc[mt][2];
        int r0 = n0 + warp * 32 + mt * 16 + (lane >> 2);
#pragma unroll
        for (int dt = 0; dt < 4; dt++) {
            int col = h * 32 + dt * 8 + 2 * (lane & 3);
            uint32_t lo = pack_bf16x2(o_[mt][dt][0] * inv0, o_[mt][dt][1] * inv0);
            uint32_t hi = pack_bf16x2(o_[mt][dt][2] * inv1, o_[mt][dt][3] * inv1);
            *(uint32_t*)&g_ao[(size_t)(b * NTOK + r0) * CH + col]     = lo;
            *(uint32_t*)&g_ao[(size_t)(b * NTOK + r0 + 8) * CH + col] = hi;
        }
    }
}

// ---------------- kernel 4: proj GEMM, m-tile 32 (R12, no smem staging) ----------------
__global__ void __launch_bounds__(128) proj_mma_kernel(const float* __restrict__ x,
                                                       const float* __restrict__ w,
                                                       const float* __restrict__ bias,
                                                       float* __restrict__ out) {
    const int b  = blockIdx.z;
    const int m0 = blockIdx.x * 32;
    const int o0 = blockIdx.y * 64;
    const int tid  = threadIdx.x;
    const int warp = tid >> 5;
    const int lane = tid & 31;
    const int mwarp = warp & 1;
    const int nwarp = warp >> 1;

    __shared__ __nv_bfloat16 As[2][32 * 40];
    __shared__ __nv_bfloat16 Bs[2][64 * 40];

    float acc[4][4];
#pragma unroll
    for (int nt = 0; nt < 4; nt++) {
#pragma unroll
        for (int c = 0; c < 4; c++) { acc[nt][c] = 0.f; }
    }

    const __nv_bfloat16* aBase = g_ao + (size_t)b * NTOK * CH;

    uint4  areg;
    float4 breg[4];
    {
        int m  = tid >> 2;
        int kk = (tid & 3) * 8;
        areg = *(const uint4*)&aBase[(size_t)(m0 + m) * CH + kk];
#pragma unroll
        for (int ii = 0; ii < 4; ii++) {
            int idx = tid + 128 * ii;
            int o   = idx >> 3;
            int kq  = (idx & 7) * 4;
            breg[ii] = *(const float4*)&w[(size_t)(o0 + o) * CH + kq];
        }
    }
    {
        int m  = tid >> 2;
        int kk = (tid & 3) * 8;
        *(uint4*)&As[0][m * 40 + kk] = areg;
#pragma unroll
        for (int ii = 0; ii < 4; ii++) {
            int idx = tid + 128 * ii;
            int o   = idx >> 3;
            int kq  = (idx & 7) * 4;
            __nv_bfloat16 tmp[4];
            tmp[0] = __float2bfloat16_rn(breg[ii].x);
            tmp[1] = __float2bfloat16_rn(breg[ii].y);
            tmp[2] = __float2bfloat16_rn(breg[ii].z);
            tmp[3] = __float2bfloat16_rn(breg[ii].w);
            *(uint2*)&Bs[0][o * 40 + kq] = *(uint2*)tmp;
        }
    }
    __syncthreads();

    const int KITERS = CH / 32;
    for (int ki = 0; ki < KITERS; ki++) {
        const int buf = ki & 1;
        if (ki + 1 < KITERS) {
            int kt = (ki + 1) * 32;
            int m  = tid >> 2;
            int kk = (tid & 3) * 8;
            areg = *(const uint4*)&aBase[(size_t)(m0 + m) * CH + kt + kk];
#pragma unroll
            for (int ii = 0; ii < 4; ii++) {
                int idx = tid + 128 * ii;
                int o   = idx >> 3;
                int kq  = (idx & 7) * 4;
                breg[ii] = *(const float4*)&w[(size_t)(o0 + o) * CH + kt + kq];
            }
        }

        uint32_t kb[4][4];
#pragma unroll
        for (int nt = 0; nt < 4; nt++) {
            uint32_t baddr = (uint32_t)__cvta_generic_to_shared(
                &Bs[buf][(nwarp * 32 + nt * 8 + (lane & 7)) * 40 + (lane >> 3) * 8]);
            ldsm_x4(kb[nt], baddr);
        }
        {
            uint32_t abase = (uint32_t)__cvta_generic_to_shared(
                &As[buf][(mwarp * 16 + (lane & 15)) * 40 + (lane >> 4) * 8]);
            uint32_t af0[4], af1[4];
            ldsm_x4(af0, abase);
            ldsm_x4(af1, abase + 32);
#pragma unroll
            for (int nt = 0; nt < 4; nt++) {
                mma16816(acc[nt], af0, kb[nt][0], kb[nt][1]);
                mma16816(acc[nt], af1, kb[nt][2], kb[nt][3]);
            }
        }

        if (ki + 1 < KITERS) {
            int m  = tid >> 2;
            int kk = (tid & 3) * 8;
            *(uint4*)&As[buf ^ 1][m * 40 + kk] = areg;
#pragma unroll
            for (int ii = 0; ii < 4; ii++) {
                int idx = tid + 128 * ii;
                int o   = idx >> 3;
                int kq  = (idx & 7) * 4;
                __nv_bfloat16 tmp[4];
                tmp[0] = __float2bfloat16_rn(breg[ii].x);
                tmp[1] = __float2bfloat16_rn(breg[ii].y);
                tmp[2] = __float2bfloat16_rn(breg[ii].z);
                tmp[3] = __float2bfloat16_rn(breg[ii].w);
                *(uint2*)&Bs[buf ^ 1][o * 40 + kq] = *(uint2*)tmp;
            }
        }
        __syncthreads();
    }

#pragma unroll
    for (int nt = 0; nt < 4; nt++) {
        int o  = o0 + nwarp * 32 + nt * 8 + 2 * (lane & 3);
        int n_lo = m0 + mwarp * 16 + (lane >> 2);
        float bp0 = __ldg(&bias[o]);
        float bp1 = __ldg(&bias[o + 1]);
        size_t i00 = (size_t)b * CH * NTOK + (size_t)o * NTOK + n_lo;
        size_t i01 = i00 + NTOK;
        out[i00]     = acc[nt][0] + x[i00]     + bp0;
        out[i01]     = acc[nt][1] + x[i01]     + bp1;
        out[i00 + 8] = acc[nt][2] + x[i00 + 8] + bp0;
        out[i01 + 8] = acc[nt][3] + x[i01 + 8] + bp1;
    }
}

// ---------------- launch ----------------
extern "C" void kernel_launch(void* const* d_in, const int* in_sizes, int n_in,
                              void* d_out, int out_size) {
    const float* x      = (const float*)d_in[0];
    const float* gamma  = (const float*)d_in[1];
    const float* beta   = (const float*)d_in[2];
    const float* w_qkv  = (const float*)d_in[3];
    const float* w_proj = (const float*)d_in[4];
    const float* b_proj = (const float*)d_in[5];
    float* out = (float*)d_out;

    ln_kernel<<<dim3(NTOK / 64, BATCH), 256>>>(x, gamma, beta);
    qkv_mma_kernel<<<dim3(NTOK / 128, 12, BATCH), 128>>>(w_qkv);
    flash_mma_kernel<<<dim3(NTOK / 128, NHEAD, BATCH), 128>>>();
    proj_mma_kernel<<<dim3(NTOK / 32, CH / 64, BATCH), 128>>>(x, w_proj, b_proj, out);
}

// round 15
// speedup vs baseline: 1.0427x; 1.0158x over previous
#include <cuda_runtime.h>
#include <cuda_bf16.h>
#include <cstdint>

#define BATCH 2
#define CH 256
#define NTOK 4096
#define NHEAD 8
#define HDIM 32
#define SCALE_LOG2E 0.2550316805267167f      // (1/sqrt(32)) * log2(e)
#define ONES_BF16X2 0x3F803F80u              // bf16 {1.0, 1.0}

// ---------------- scratch (no allocations allowed) ----------------
__device__ __nv_bfloat16 g_tn[BATCH * CH * NTOK];               // layernorm out, [b][c][n] bf16
__device__ uint8_t       g_q8[BATCH * NHEAD * NTOK * HDIM];     // e4m3, pre-scaled by SCALE_LOG2E
__device__ uint8_t       g_k8[BATCH * NHEAD * NTOK * HDIM];     // e4m3
__device__ __nv_bfloat16 g_v [BATCH * NHEAD * NTOK * HDIM];     // bf16
__device__ __nv_bfloat16 g_ao[BATCH * NTOK * CH];               // attn out, [b][n][c] bf16

// ---------------- helpers ----------------
__device__ __forceinline__ void ldsm_x4(uint32_t* r, uint32_t saddr) {
    asm volatile("ldmatrix.sync.aligned.m8n8.x4.shared.b16 {%0,%1,%2,%3}, [%4];"
                 : "=r"(r[0]), "=r"(r[1]), "=r"(r[2]), "=r"(r[3]) : "r"(saddr));
}
__device__ __forceinline__ void ldsm_x4_trans(uint32_t* r, uint32_t saddr) {
    asm volatile("ldmatrix.sync.aligned.m8n8.x4.trans.shared.b16 {%0,%1,%2,%3}, [%4];"
                 : "=r"(r[0]), "=r"(r[1]), "=r"(r[2]), "=r"(r[3]) : "r"(saddr));
}
__device__ __forceinline__ void mma16816(float* c, const uint32_t* a, uint32_t b0, uint32_t b1) {
    asm volatile("mma.sync.aligned.m16n8k16.row.col.f32.bf16.bf16.f32 "
                 "{%0,%1,%2,%3}, {%4,%5,%6,%7}, {%8,%9}, {%0,%1,%2,%3};"
                 : "+f"(c[0]), "+f"(c[1]), "+f"(c[2]), "+f"(c[3])
                 : "r"(a[0]), "r"(a[1]), "r"(a[2]), "r"(a[3]), "r"(b0), "r"(b1));
}
__device__ __forceinline__ void mma16832_fp8(float* c, const uint32_t* a, uint32_t b0, uint32_t b1) {
    asm volatile("mma.sync.aligned.m16n8k32.row.col.f32.e4m3.e4m3.f32 "
                 "{%0,%1,%2,%3}, {%4,%5,%6,%7}, {%8,%9}, {%0,%1,%2,%3};"
                 : "+f"(c[0]), "+f"(c[1]), "+f"(c[2]), "+f"(c[3])
                 : "r"(a[0]), "r"(a[1]), "r"(a[2]), "r"(a[3]), "r"(b0), "r"(b1));
}
__device__ __forceinline__ uint32_t pack_bf16x2(float lo, float hi) {
    uint32_t r;
    asm("cvt.rn.bf16x2.f32 %0, %1, %2;" : "=r"(r) : "f"(hi), "f"(lo));
    return r;
}
__device__ __forceinline__ uint16_t pack_e4m3x2(float lo, float hi) {
    uint16_t r;
    asm("cvt.rn.satfinite.e4m3x2.f32 %0, %1, %2;" : "=h"(r) : "f"(hi), "f"(lo));
    return r;
}
__device__ __forceinline__ uint32_t ex2_bf16x2(uint32_t u) {
    uint32_t r;
    asm("ex2.approx.ftz.bf16x2 %0, %1;" : "=r"(r) : "r"(u));
    return r;
}
__device__ __forceinline__ void cp_async16(uint32_t saddr, const void* gptr) {
    asm volatile("cp.async.cg.shared.global [%0], [%1], 16;" :: "r"(saddr), "l"(gptr));
}
#define CP_COMMIT() asm volatile("cp.async.commit_group;")
#define CP_WAIT1()  asm volatile("cp.async.wait_group 1;")

// ---------------- kernel 1: LayerNorm, block-parallel (R8) ----------------
__global__ void __launch_bounds__(256) ln_kernel(const float* __restrict__ x,
                                                 const float* __restrict__ gamma,
                                                 const float* __restrict__ beta) {
    const int b   = blockIdx.y;
    const int n0  = blockIdx.x * 64;
    const int tid = threadIdx.x;
    const int tok = tid & 63;
    const int grp = tid >> 6;

    __shared__ float red_s [4][64];
    __shared__ float red_ss[4][64];
    __shared__ float mu_s[64], rs_s[64];

    const float* xb = x + (size_t)b * CH * NTOK + n0 + tok;

    float s = 0.f, ss = 0.f;
#pragma unroll 16
    for (int i = 0; i < 64; i++) {
        float v = xb[(size_t)(grp * 64 + i) * NTOK];
        s += v; ss += v * v;
    }
    red_s[grp][tok]  = s;
    red_ss[grp][tok] = ss;
    __syncthreads();

    if (tid < 64) {
        float st = red_s[0][tid] + red_s[1][tid] + red_s[2][tid] + red_s[3][tid];
        float sst = red_ss[0][tid] + red_ss[1][tid] + red_ss[2][tid] + red_ss[3][tid];
        float mu = st * (1.0f / CH);
        float var = sst * (1.0f / CH) - mu * mu;
        mu_s[tid] = mu;
        rs_s[tid] = rsqrtf(var + 1e-5f);
    }
    __syncthreads();

    const float mu = mu_s[tok];
    const float rs = rs_s[tok];
    __nv_bfloat16* tb = g_tn + (size_t)b * CH * NTOK + n0 + tok;
#pragma unroll 16
    for (int i = 0; i < 64; i++) {
        int c = grp * 64 + i;
        float v = xb[(size_t)c * NTOK];
        tb[(size_t)c * NTOK] = __float2bfloat16_rn((v - mu) * rs * __ldg(&gamma[c]) + __ldg(&beta[c]));
    }
}

// ---------------- kernel 2: QKV GEMM, register-staged; q/k -> e4m3, v -> bf16 (R12) ----------------
__global__ void __launch_bounds__(128) qkv_mma_kernel(const float* __restrict__ w) {
    const int b  = blockIdx.z;
    const int m0 = blockIdx.x * 128;
    const int o0 = blockIdx.y * 64;
    const int tid  = threadIdx.x;
    const int warp = tid >> 5;
    const int lane = tid & 31;

    __shared__ __nv_bfloat16 As[2][32 * 136];
    __shared__ __nv_bfloat16 Bs[2][64 * 40];

    float acc[2][8][4];
#pragma unroll
    for (int mt = 0; mt < 2; mt++) {
#pragma unroll
        for (int nt = 0; nt < 8; nt++) {
#pragma unroll
            for (int c = 0; c < 4; c++) { acc[mt][nt][c] = 0.f; }
        }
    }

    const __nv_bfloat16* aBase = g_tn + (size_t)b * CH * NTOK;

    uint4  areg[4];
    float4 breg[4];
#pragma unroll
    for (int ii = 0; ii < 4; ii++) {
        int idx = tid + 128 * ii;
        int k   = idx >> 4;
        int mc  = (idx & 15) * 8;
        areg[ii] = *(const uint4*)&aBase[(size_t)k * NTOK + m0 + mc];
        int o   = idx >> 3;
        int kk  = (idx & 7) * 4;
        breg[ii] = *(const float4*)&w[(size_t)(o0 + o) * CH + kk];
    }
#pragma unroll
    for (int ii = 0; ii < 4; ii++) {
        int idx = tid + 128 * ii;
        int k   = idx >> 4;
        int mc  = (idx & 15) * 8;
        *(uint4*)&As[0][k * 136 + mc] = areg[ii];
        int o   = idx >> 3;
        int kk  = (idx & 7) * 4;
        __nv_bfloat16 tmp[4];
        tmp[0] = __float2bfloat16_rn(breg[ii].x);
        tmp[1] = __float2bfloat16_rn(breg[ii].y);
        tmp[2] = __float2bfloat16_rn(breg[ii].z);
        tmp[3] = __float2bfloat16_rn(breg[ii].w);
        *(uint2*)&Bs[0][o * 40 + kk] = *(uint2*)tmp;
    }
    __syncthreads();

    const int KITERS = CH / 32;
    for (int ki = 0; ki < KITERS; ki++) {
        const int buf = ki & 1;
        if (ki + 1 < KITERS) {
            int kt = (ki + 1) * 32;
#pragma unroll
            for (int ii = 0; ii < 4; ii++) {
                int idx = tid + 128 * ii;
                int k   = idx >> 4;
                int mc  = (idx & 15) * 8;
                areg[ii] = *(const uint4*)&aBase[(size_t)(kt + k) * NTOK + m0 + mc];
                int o   = idx >> 3;
                int kk  = (idx & 7) * 4;
                breg[ii] = *(const float4*)&w[(size_t)(o0 + o) * CH + kt + kk];
            }
        }

        uint32_t kb[8][4];
#pragma unroll
        for (int nt = 0; nt < 8; nt++) {
            uint32_t baddr = (uint32_t)__cvta_generic_to_shared(
                &Bs[buf][(nt * 8 + (lane & 7)) * 40 + (lane >> 3) * 8]);
            ldsm_x4(kb[nt], baddr);
        }
#pragma unroll
        for (int ks = 0; ks < 2; ks++) {
            uint32_t af[2][4];
#pragma unroll
            for (int mt = 0; mt < 2; mt++) {
                int mrow0 = warp * 32 + mt * 16;
                uint32_t aaddr = (uint32_t)__cvta_generic_to_shared(
                    &As[buf][(ks * 16 + (lane & 7) + ((lane & 16) >> 1)) * 136 + mrow0 + (lane & 8)]);
                ldsm_x4_trans(af[mt], aaddr);
            }
#pragma unroll
            for (int mt = 0; mt < 2; mt++) {
#pragma unroll
                for (int nt = 0; nt < 8; nt++) {
                    mma16816(acc[mt][nt], af[mt], kb[nt][2 * ks], kb[nt][2 * ks + 1]);
                }
            }
        }

        if (ki + 1 < KITERS) {
#pragma unroll
            for (int ii = 0; ii < 4; ii++) {
                int idx = tid + 128 * ii;
                int k   = idx >> 4;
                int mc  = (idx & 15) * 8;
                *(uint4*)&As[buf ^ 1][k * 136 + mc] = areg[ii];
                int o   = idx >> 3;
                int kk  = (idx & 7) * 4;
                __nv_bfloat16 tmp[4];
                tmp[0] = __float2bfloat16_rn(breg[ii].x);
                tmp[1] = __float2bfloat16_rn(breg[ii].y);
                tmp[2] = __float2bfloat16_rn(breg[ii].z);
                tmp[3] = __float2bfloat16_rn(breg[ii].w);
                *(uint2*)&Bs[buf ^ 1][o * 40 + kk] = *(uint2*)tmp;
            }
        }
        __syncthreads();
    }

    const int which = o0 >> 8;                   // 0:q 1:k 2:v
    if (which < 2) {
        const float sc = (which == 0) ? SCALE_LOG2E : 1.0f;
        uint8_t* outp = (which == 0) ? g_q8 : g_k8;
#pragma unroll
        for (int mt = 0; mt < 2; mt++) {
#pragma unroll
            for (int nt = 0; nt < 8; nt++) {
                int o  = o0 + nt * 8 + 2 * (lane & 3);
                int h  = (o >> 5) & 7;
                int dd = o & 31;
                int n_lo = m0 + warp * 32 + mt * 16 + (lane >> 2);
                uint16_t lo = pack_e4m3x2(acc[mt][nt][0] * sc, acc[mt][nt][1] * sc);
                uint16_t hi = pack_e4m3x2(acc[mt][nt][2] * sc, acc[mt][nt][3] * sc);
                *(uint16_t*)&outp[((size_t)(b * NHEAD + h) * NTOK + n_lo) * HDIM + dd]     = lo;
                *(uint16_t*)&outp[((size_t)(b * NHEAD + h) * NTOK + n_lo + 8) * HDIM + dd] = hi;
            }
        }
    } else {
#pragma unroll
        for (int mt = 0; mt < 2; mt++) {
#pragma unroll
            for (int nt = 0; nt < 8; nt++) {
                int o  = o0 + nt * 8 + 2 * (lane & 3);
                int h  = (o >> 5) & 7;
                int dd = o & 31;
                int n_lo = m0 + warp * 32 + mt * 16 + (lane >> 2);
                uint32_t lo = pack_bf16x2(acc[mt][nt][0], acc[mt][nt][1]);
                uint32_t hi = pack_bf16x2(acc[mt][nt][2], acc[mt][nt][3]);
                *(uint32_t*)&g_v[((size_t)(b * NHEAD + h) * NTOK + n_lo) * HDIM + dd]     = lo;
                *(uint32_t*)&g_v[((size_t)(b * NHEAD + h) * NTOK + n_lo + 8) * HDIM + dd] = hi;
            }
        }
    }
}

// ---------------- kernel 3: flash attention, fused chunk loop, forced 4 CTAs/SM ----------------
// BM=128 / BN=128, no softmax. __launch_bounds__(128, 4) caps regs at 128 so the 54KB-smem
// occupancy limit (4 CTAs/SM, 16 warps) is actually reached; V ldsm hoisted next to K ldsm
// to fill the QK-mma -> ex2 latency window with independent work.
__global__ void __launch_bounds__(128, 4) flash_mma_kernel() {
    const int b  = blockIdx.z;
    const int h  = blockIdx.y;
    const int n0 = blockIdx.x * 128;
    const int tid  = threadIdx.x;
    const int warp = tid >> 5;
    const int lane = tid & 31;

    __shared__ uint8_t       Qs[128 * 48];
    __shared__ uint8_t       Ks[3][128 * 48];
    __shared__ __nv_bfloat16 Vs[3][128 * 40];

    const uint8_t* qsrc = g_q8 + ((size_t)(b * NHEAD + h) * NTOK + n0) * HDIM;
    const uint8_t* ksrc = g_k8 + (size_t)(b * NHEAD + h) * NTOK * HDIM;
    const __nv_bfloat16* vsrc = g_v + (size_t)(b * NHEAD + h) * NTOK * HDIM;

#pragma unroll
    for (int ii = 0; ii < 2; ii++) {
        int idx = tid + 128 * ii;
        int row = idx >> 1;
        int cc  = idx & 1;
        *(uint4*)&Qs[row * 48 + cc * 16] = *(const uint4*)&qsrc[(size_t)row * 32 + cc * 16];
    }

#pragma unroll
    for (int stg = 0; stg < 2; stg++) {
        int j = stg * 128;
#pragma unroll
        for (int ii = 0; ii < 2; ii++) {
            int idx = tid + 128 * ii;
            int row = idx >> 1;
            int cc  = idx & 1;
            cp_async16((uint32_t)__cvta_generic_to_shared(&Ks[stg][row * 48 + cc * 16]),
                       &ksrc[(size_t)(j + row) * 32 + cc * 16]);
        }
#pragma unroll
        for (int ii = 0; ii < 4; ii++) {
            int idx = tid + 128 * ii;
            int row = idx >> 2;
            int cc  = idx & 3;
            cp_async16((uint32_t)__cvta_generic_to_shared(&Vs[stg][row * 40 + cc * 8]),
                       &vsrc[(size_t)(j + row) * 32 + cc * 8]);
        }
        CP_COMMIT();
    }
    __syncthreads();

    uint32_t aq[2][4];
#pragma unroll
    for (int mt = 0; mt < 2; mt++) {
        uint32_t base = (uint32_t)__cvta_generic_to_shared(
            &Qs[(warp * 32 + mt * 16 + (lane & 15)) * 48 + (lane >> 4) * 16]);
        ldsm_x4(aq[mt], base);
    }

    float lacc[2][4];
    float o_[2][4][4];
#pragma unroll
    for (int mt = 0; mt < 2; mt++) {
#pragma unroll
        for (int c = 0; c < 4; c++) { lacc[mt][c] = 0.f; }
#pragma unroll
        for (int dt = 0; dt < 4; dt++) {
#pragma unroll
            for (int c = 0; c < 4; c++) { o_[mt][dt][c] = 0.f; }
        }
    }

    const int NITER = NTOK / 128;   // 32
    int st = 0;
    for (int it = 0; it < NITER; it++) {
        CP_WAIT1();
        __syncthreads();

        if (it + 2 < NITER) {
            int stn = (st + 2 >= 3) ? st - 1 : st + 2;
            int j = (it + 2) * 128;
#pragma unroll
            for (int ii = 0; ii < 2; ii++) {
                int idx = tid + 128 * ii;
                int row = idx >> 1;
                int cc  = idx & 1;
                cp_async16((uint32_t)__cvta_generic_to_shared(&Ks[stn][row * 48 + cc * 16]),
                           &ksrc[(size_t)(j + row) * 32 + cc * 16]);
            }
#pragma unroll
            for (int ii = 0; ii < 4; ii++) {
                int idx = tid + 128 * ii;
                int row = idx >> 2;
                int cc  = idx & 3;
                cp_async16((uint32_t)__cvta_generic_to_shared(&Vs[stn][row * 40 + cc * 8]),
                           &vsrc[(size_t)(j + row) * 32 + cc * 8]);
            }
        }
        CP_COMMIT();

        const uint8_t* KsS = Ks[st];
        const __nv_bfloat16* VsS = Vs[st];
        st = (st + 1 == 3) ? 0 : st + 1;

        // fused per-chunk: ldsm K -> QK mma -> ldsm V (independent) -> ex2 -> l -> PV
#pragma unroll
        for (int ntp = 0; ntp < 8; ntp++) {
            uint32_t kbf[4];
            uint32_t kaddr = (uint32_t)__cvta_generic_to_shared(
                &KsS[(ntp * 16 + (lane & 15)) * 48 + (lane >> 4) * 16]);
            ldsm_x4(kbf, kaddr);

            float s0a[4] = {0.f, 0.f, 0.f, 0.f};
            float s1a[4] = {0.f, 0.f, 0.f, 0.f};
            float s0b[4] = {0.f, 0.f, 0.f, 0.f};
            float s1b[4] = {0.f, 0.f, 0.f, 0.f};
            mma16832_fp8(s0a, aq[0], kbf[0], kbf[2]);
            mma16832_fp8(s1a, aq[0], kbf[1], kbf[3]);
            mma16832_fp8(s0b, aq[1], kbf[0], kbf[2]);
            mma16832_fp8(s1b, aq[1], kbf[1], kbf[3]);

            // independent V loads fill the mma->ex2 latency window
            uint32_t vb0[4], vb1[4];
            uint32_t vaddr = (uint32_t)__cvta_generic_to_shared(
                &VsS[(ntp * 16 + (lane & 15)) * 40 + (lane >> 4) * 8]);
            ldsm_x4_trans(vb0, vaddr);
            ldsm_x4_trans(vb1, vaddr + 32);   // d 16..31 (+16 elems)

            uint32_t pa[2][4];
            pa[0][0] = ex2_bf16x2(pack_bf16x2(s0a[0], s0a[1]));
            pa[0][1] = ex2_bf16x2(pack_bf16x2(s0a[2], s0a[3]));
            pa[0][2] = ex2_bf16x2(pack_bf16x2(s1a[0], s1a[1]));
            pa[0][3] = ex2_bf16x2(pack_bf16x2(s1a[2], s1a[3]));
            pa[1][0] = ex2_bf16x2(pack_bf16x2(s0b[0], s0b[1]));
            pa[1][1] = ex2_bf16x2(pack_bf16x2(s0b[2], s0b[3]));
            pa[1][2] = ex2_bf16x2(pack_bf16x2(s1b[0], s1b[1]));
            pa[1][3] = ex2_bf16x2(pack_bf16x2(s1b[2], s1b[3]));

#pragma unroll
            for (int mt = 0; mt < 2; mt++) {
                mma16816(lacc[mt], pa[mt], ONES_BF16X2, ONES_BF16X2);
                mma16816(o_[mt][0], pa[mt], vb0[0], vb0[1]);
                mma16816(o_[mt][1], pa[mt], vb0[2], vb0[3]);
                mma16816(o_[mt][2], pa[mt], vb1[0], vb1[1]);
                mma16816(o_[mt][3], pa[mt], vb1[2], vb1[3]);
            }
        }
    }

#pragma unroll
    for (int mt = 0; mt < 2; mt++) {
        float inv0 = 1.0f / lacc[mt][0];
        float inv1 = 1.0f / lacc[mt][2];
        int r0 = n0 + warp * 32 + mt * 16 + (lane >> 2);
#pragma unroll
        for (int dt = 0; dt < 4; dt++) {
            int col = h * 32 + dt * 8 + 2 * (lane & 3);
            uint32_t lo = pack_bf16x2(o_[mt][dt][0] * inv0, o_[mt][dt][1] * inv0);
            uint32_t hi = pack_bf16x2(o_[mt][dt][2] * inv1, o_[mt][dt][3] * inv1);
            *(uint32_t*)&g_ao[(size_t)(b * NTOK + r0) * CH + col]     = lo;
            *(uint32_t*)&g_ao[(size_t)(b * NTOK + r0 + 8) * CH + col] = hi;
        }
    }
}

// ---------------- kernel 4: proj GEMM, m-tile 32 (R12) ----------------
__global__ void __launch_bounds__(128) proj_mma_kernel(const float* __restrict__ x,
                                                       const float* __restrict__ w,
                                                       const float* __restrict__ bias,
                                                       float* __restrict__ out) {
    const int b  = blockIdx.z;
    const int m0 = blockIdx.x * 32;
    const int o0 = blockIdx.y * 64;
    const int tid  = threadIdx.x;
    const int warp = tid >> 5;
    const int lane = tid & 31;
    const int mwarp = warp & 1;
    const int nwarp = warp >> 1;

    __shared__ __nv_bfloat16 As[2][32 * 40];
    __shared__ __nv_bfloat16 Bs[2][64 * 40];

    float acc[4][4];
#pragma unroll
    for (int nt = 0; nt < 4; nt++) {
#pragma unroll
        for (int c = 0; c < 4; c++) { acc[nt][c] = 0.f; }
    }

    const __nv_bfloat16* aBase = g_ao + (size_t)b * NTOK * CH;

    uint4  areg;
    float4 breg[4];
    {
        int m  = tid >> 2;
        int kk = (tid & 3) * 8;
        areg = *(const uint4*)&aBase[(size_t)(m0 + m) * CH + kk];
#pragma unroll
        for (int ii = 0; ii < 4; ii++) {
            int idx = tid + 128 * ii;
            int o   = idx >> 3;
            int kq  = (idx & 7) * 4;
            breg[ii] = *(const float4*)&w[(size_t)(o0 + o) * CH + kq];
        }
    }
    {
        int m  = tid >> 2;
        int kk = (tid & 3) * 8;
        *(uint4*)&As[0][m * 40 + kk] = areg;
#pragma unroll
        for (int ii = 0; ii < 4; ii++) {
            int idx = tid + 128 * ii;
            int o   = idx >> 3;
            int kq  = (idx & 7) * 4;
            __nv_bfloat16 tmp[4];
            tmp[0] = __float2bfloat16_rn(breg[ii].x);
            tmp[1] = __float2bfloat16_rn(breg[ii].y);
            tmp[2] = __float2bfloat16_rn(breg[ii].z);
            tmp[3] = __float2bfloat16_rn(breg[ii].w);
            *(uint2*)&Bs[0][o * 40 + kq] = *(uint2*)tmp;
        }
    }
    __syncthreads();

    const int KITERS = CH / 32;
    for (int ki = 0; ki < KITERS; ki++) {
        const int buf = ki & 1;
        if (ki + 1 < KITERS) {
            int kt = (ki + 1) * 32;
            int m  = tid >> 2;
            int kk = (tid & 3) * 8;
            areg = *(const uint4*)&aBase[(size_t)(m0 + m) * CH + kt + kk];
#pragma unroll
            for (int ii = 0; ii < 4; ii++) {
                int idx = tid + 128 * ii;
                int o   = idx >> 3;
                int kq  = (idx & 7) * 4;
                breg[ii] = *(const float4*)&w[(size_t)(o0 + o) * CH + kt + kq];
            }
        }

        uint32_t kb[4][4];
#pragma unroll
        for (int nt = 0; nt < 4; nt++) {
            uint32_t baddr = (uint32_t)__cvta_generic_to_shared(
                &Bs[buf][(nwarp * 32 + nt * 8 + (lane & 7)) * 40 + (lane >> 3) * 8]);
            ldsm_x4(kb[nt], baddr);
        }
        {
            uint32_t abase = (uint32_t)__cvta_generic_to_shared(
                &As[buf][(mwarp * 16 + (lane & 15)) * 40 + (lane >> 4) * 8]);
            uint32_t af0[4], af1[4];
            ldsm_x4(af0, abase);
            ldsm_x4(af1, abase + 32);
#pragma unroll
            for (int nt = 0; nt < 4; nt++) {
                mma16816(acc[nt], af0, kb[nt][0], kb[nt][1]);
                mma16816(acc[nt], af1, kb[nt][2], kb[nt][3]);
            }
        }

        if (ki + 1 < KITERS) {
            int m  = tid >> 2;
            int kk = (tid & 3) * 8;
            *(uint4*)&As[buf ^ 1][m * 40 + kk] = areg;
#pragma unroll
            for (int ii = 0; ii < 4; ii++) {
                int idx = tid + 128 * ii;
                int o   = idx >> 3;
                int kq  = (idx & 7) * 4;
                __nv_bfloat16 tmp[4];
                tmp[0] = __float2bfloat16_rn(breg[ii].x);
                tmp[1] = __float2bfloat16_rn(breg[ii].y);
                tmp[2] = __float2bfloat16_rn(breg[ii].z);
                tmp[3] = __float2bfloat16_rn(breg[ii].w);
                *(uint2*)&Bs[buf ^ 1][o * 40 + kq] = *(uint2*)tmp;
            }
        }
        __syncthreads();
    }

#pragma unroll
    for (int nt = 0; nt < 4; nt++) {
        int o  = o0 + nwarp * 32 + nt * 8 + 2 * (lane & 3);
        int n_lo = m0 + mwarp * 16 + (lane >> 2);
        float bp0 = __ldg(&bias[o]);
        float bp1 = __ldg(&bias[o + 1]);
        size_t i00 = (size_t)b * CH * NTOK + (size_t)o * NTOK + n_lo;
        size_t i01 = i00 + NTOK;
        out[i00]     = acc[nt][0] + x[i00]     + bp0;
        out[i01]     = acc[nt][1] + x[i01]     + bp1;
        out[i00 + 8] = acc[nt][2] + x[i00 + 8] + bp0;
        out[i01 + 8] = acc[nt][3] + x[i01 + 8] + bp1;
    }
}

// ---------------- launch ----------------
extern "C" void kernel_launch(void* const* d_in, const int* in_sizes, int n_in,
                              void* d_out, int out_size) {
    const float* x      = (const float*)d_in[0];
    const float* gamma  = (const float*)d_in[1];
    const float* beta   = (const float*)d_in[2];
    const float* w_qkv  = (const float*)d_in[3];
    const float* w_proj = (const float*)d_in[4];
    const float* b_proj = (const float*)d_in[5];
    float* out = (float*)d_out;

    ln_kernel<<<dim3(NTOK / 64, BATCH), 256>>>(x, gamma, beta);
    qkv_mma_kernel<<<dim3(NTOK / 128, 12, BATCH), 128>>>(w_qkv);
    flash_mma_kernel<<<dim3(NTOK / 128, NHEAD, BATCH), 128>>>();
    proj_mma_kernel<<<dim3(NTOK / 32, CH / 64, BATCH), 128>>>(x, w_proj, b_proj, out);
}